// round 1
// baseline (speedup 1.0000x reference)
#include <cuda_runtime.h>

#define FEAT 256
#define N_MAX 50000

// Scratch (static device globals — no allocation allowed in kernel_launch)
__device__ float g_y[(size_t)N_MAX * FEAT];   // (x @ W) * dinv[row]
__device__ float g_deg[N_MAX];
__device__ float g_dinv[N_MAX];
__device__ int   g_is64;

// ---------------------------------------------------------------------------
// Edge-index dtype probe: reference declares int64, but JAX without x64 may
// deliver int32. If int64, the high 32-bit word of each (nonnegative, <2^31)
// value is 0. Check 512 entries; P(false positive with int32 uniform [0,50000))
// is ~0. Deterministic given input.
// ---------------------------------------------------------------------------
__global__ void detect_dtype_kernel(const int* __restrict__ e) {
    __shared__ int any_nonzero;
    if (threadIdx.x == 0) any_nonzero = 0;
    __syncthreads();
    int local = 0;
    for (int i = threadIdx.x; i < 512; i += blockDim.x)
        if (e[2 * i + 1] != 0) local = 1;
    if (local) atomicExch(&any_nonzero, 1);
    __syncthreads();
    if (threadIdx.x == 0) g_is64 = any_nonzero ? 0 : 1;
}

__device__ __forceinline__ int load_idx(const void* e, long long i, long long E, bool dst) {
    if (g_is64) {
        const long long* p = (const long long*)e;
        return (int)p[(dst ? E : 0) + i];
    } else {
        const int* p = (const int*)e;
        return p[(dst ? E : 0) + i];
    }
}

// ---------------------------------------------------------------------------
// Degree (incl. self-loop) and dinv = rsqrt(deg)
// ---------------------------------------------------------------------------
__global__ void init_deg_kernel(int n) {
    int i = blockIdx.x * blockDim.x + threadIdx.x;
    if (i < n) g_deg[i] = 1.0f;  // self-loop
}

__global__ void count_deg_kernel(const void* __restrict__ e, int E) {
    int i = blockIdx.x * blockDim.x + threadIdx.x;
    if (i >= E) return;
    int d = load_idx(e, i, E, true);
    atomicAdd(&g_deg[d], 1.0f);
}

__global__ void dinv_kernel(int n) {
    int i = blockIdx.x * blockDim.x + threadIdx.x;
    if (i < n) g_dinv[i] = rsqrtf(g_deg[i]);
}

// ---------------------------------------------------------------------------
// GEMM: y[r][c] = dinv[r] * sum_k x[r][k] * W[k][c]
// Epilogue also seeds out[r][c] = y[r][c] * dinv[r]  (self-loop message),
// saving a full 51 MB init pass over out.
// Tile: BM=128, BN=64, BK=32, 256 threads, 8x4 register tile per thread.
// ---------------------------------------------------------------------------
#define BM 128
#define BN 64
#define BK 32

__global__ __launch_bounds__(256) void gemm_scale_kernel(
    const float* __restrict__ x, const float* __restrict__ W,
    float* __restrict__ out, int M)
{
    __shared__ float As[BK][BM + 4];  // transposed A tile; row=132 floats (16B-aligned)
    __shared__ float Bs[BK][BN];

    const int bm = blockIdx.x * BM;
    const int bn = blockIdx.y * BN;
    const int tid = threadIdx.x;
    const int tx = tid % 16;          // col group (4 cols)
    const int ty = tid / 16;          // row group (8 rows)

    // A-load mapping: 128 rows x 32 cols / 256 thr = 4 float4 each
    const int arow = tid / 8;         // 0..31
    const int acol = (tid % 8) * 4;   // 0..28
    // B-load mapping: 32 rows x 64 cols / 256 thr = 2 float4 each
    const int brow = tid / 16;        // 0..15
    const int bcol = (tid % 16) * 4;  // 0..60

    float acc[8][4];
#pragma unroll
    for (int i = 0; i < 8; i++)
#pragma unroll
        for (int j = 0; j < 4; j++) acc[i][j] = 0.0f;

    for (int k0 = 0; k0 < FEAT; k0 += BK) {
#pragma unroll
        for (int i = 0; i < 4; i++) {
            int r = bm + arow + i * 32;
            float4 v = make_float4(0.f, 0.f, 0.f, 0.f);
            if (r < M) v = *(const float4*)(x + (size_t)r * FEAT + k0 + acol);
            As[acol + 0][arow + i * 32] = v.x;
            As[acol + 1][arow + i * 32] = v.y;
            As[acol + 2][arow + i * 32] = v.z;
            As[acol + 3][arow + i * 32] = v.w;
        }
#pragma unroll
        for (int i = 0; i < 2; i++) {
            int r = k0 + brow + i * 16;
            *(float4*)&Bs[brow + i * 16][bcol] =
                *(const float4*)(W + (size_t)r * FEAT + bn + bcol);
        }
        __syncthreads();

#pragma unroll
        for (int k = 0; k < BK; k++) {
            float4 a0 = *(const float4*)&As[k][ty * 8];
            float4 a1 = *(const float4*)&As[k][ty * 8 + 4];
            float4 bb = *(const float4*)&Bs[k][tx * 4];
            float a[8] = {a0.x, a0.y, a0.z, a0.w, a1.x, a1.y, a1.z, a1.w};
            float b[4] = {bb.x, bb.y, bb.z, bb.w};
#pragma unroll
            for (int i = 0; i < 8; i++)
#pragma unroll
                for (int j = 0; j < 4; j++) acc[i][j] = fmaf(a[i], b[j], acc[i][j]);
        }
        __syncthreads();
    }

#pragma unroll
    for (int i = 0; i < 8; i++) {
        int r = bm + ty * 8 + i;
        if (r < M) {
            float dv = g_dinv[r];
            float4 v;
            v.x = acc[i][0] * dv; v.y = acc[i][1] * dv;
            v.z = acc[i][2] * dv; v.w = acc[i][3] * dv;
            *(float4*)(g_y + (size_t)r * FEAT + bn + tx * 4) = v;
            float4 v2;
            v2.x = v.x * dv; v2.y = v.y * dv; v2.z = v.z * dv; v2.w = v.w * dv;
            *(float4*)(out + (size_t)r * FEAT + bn + tx * 4) = v2;
        }
    }
}

// ---------------------------------------------------------------------------
// Edge scatter: one warp per edge. out[dst] += y[src] * dinv[dst]
// Coalesced float4 gather of the 1KB source row; vector f32 reductions
// (red.global.add.v4.f32, sm_90+) cut L2-atomic op count 4x vs scalar.
// ---------------------------------------------------------------------------
__device__ __forceinline__ void red_add_v4(float* addr, float4 v) {
    asm volatile("red.global.add.v4.f32 [%0], {%1, %2, %3, %4};"
                 :: "l"(addr), "f"(v.x), "f"(v.y), "f"(v.z), "f"(v.w)
                 : "memory");
}

__global__ __launch_bounds__(256) void edge_scatter_kernel(
    const void* __restrict__ e, float* __restrict__ out, int E)
{
    int warp = (blockIdx.x * blockDim.x + threadIdx.x) >> 5;
    int lane = threadIdx.x & 31;
    if (warp >= E) return;

    int s = load_idx(e, warp, E, false);
    int d = load_idx(e, warp, E, true);
    float scale = g_dinv[d];

    const float4* yrow = (const float4*)(g_y + (size_t)s * FEAT);
    float*        orow = out + (size_t)d * FEAT;

#pragma unroll
    for (int i = 0; i < 2; i++) {
        int c4 = lane + 32 * i;            // float4 index within the row (0..63)
        float4 v = yrow[c4];
        v.x *= scale; v.y *= scale; v.z *= scale; v.w *= scale;
        red_add_v4(orow + 4 * c4, v);
    }
}

// ---------------------------------------------------------------------------
// Finalize: out = relu(out + b)
// ---------------------------------------------------------------------------
__global__ void finalize_kernel(float* __restrict__ out, const float* __restrict__ b,
                                int total4)
{
    int i = blockIdx.x * blockDim.x + threadIdx.x;
    if (i >= total4) return;
    float4 v = ((float4*)out)[i];
    float4 bb = ((const float4*)b)[i & 63];  // 64 float4 per 256-wide row
    v.x = fmaxf(v.x + bb.x, 0.0f);
    v.y = fmaxf(v.y + bb.y, 0.0f);
    v.z = fmaxf(v.z + bb.z, 0.0f);
    v.w = fmaxf(v.w + bb.w, 0.0f);
    ((float4*)out)[i] = v;
}

// ---------------------------------------------------------------------------
// Launch
// ---------------------------------------------------------------------------
extern "C" void kernel_launch(void* const* d_in, const int* in_sizes, int n_in,
                              void* d_out, int out_size)
{
    const float* x  = (const float*)d_in[0];
    const void*  e  = d_in[1];                 // int64 or int32, probed on-device
    const float* W  = (const float*)d_in[2];
    const float* b  = (const float*)d_in[3];
    float* out = (float*)d_out;

    const int N = in_sizes[0] / FEAT;          // 50000
    const int E = in_sizes[1] / 2;             // 1,600,000

    detect_dtype_kernel<<<1, 256>>>((const int*)e);

    init_deg_kernel<<<(N + 255) / 256, 256>>>(N);
    count_deg_kernel<<<(E + 255) / 256, 256>>>(e, E);
    dinv_kernel<<<(N + 255) / 256, 256>>>(N);

    dim3 ggrid((N + BM - 1) / BM, FEAT / BN);
    gemm_scale_kernel<<<ggrid, 256>>>(x, W, out, N);

    long long total_threads = (long long)E * 32;
    int sblocks = (int)((total_threads + 255) / 256);
    edge_scatter_kernel<<<sblocks, 256>>>(e, out, E);

    int total4 = N * (FEAT / 4);
    finalize_kernel<<<(total4 + 255) / 256, 256>>>(out, b, total4);
}

// round 4
// speedup vs baseline: 1.4155x; 1.4155x over previous
#include <cuda_runtime.h>
#include <cuda_bf16.h>
#include <stdint.h>

#define FEAT 256
#define N_MAXN 50176
#define E_MAXE 1605632

// ---------------- device scratch (static; no allocation allowed) ------------
__device__ float g_y[(size_t)N_MAXN * FEAT];     // xw * dinv[row]
__device__ int   g_deg[N_MAXN];
__device__ float g_dinv[N_MAXN];
__device__ int   g_off[N_MAXN + 1];
__device__ int   g_cursor[N_MAXN];
__device__ int   g_srcs[E_MAXE];
__device__ int   g_is64;

// ---------------------------------------------------------------------------
// Edge-index dtype probe (int64 per reference, but JAX may emit int32).
// If int64 with values < 2^31, every high word is 0. Deterministic.
// ---------------------------------------------------------------------------
__global__ void detect_dtype_kernel(const int* __restrict__ e) {
    __shared__ int any_nonzero;
    if (threadIdx.x == 0) any_nonzero = 0;
    __syncthreads();
    int local = 0;
    for (int i = threadIdx.x; i < 512; i += blockDim.x)
        if (e[2 * i + 1] != 0) local = 1;
    if (local) atomicExch(&any_nonzero, 1);
    __syncthreads();
    if (threadIdx.x == 0) g_is64 = any_nonzero ? 0 : 1;
}

__device__ __forceinline__ int load_idx(const void* e, long long i, long long E, bool dst) {
    if (g_is64) {
        const long long* p = (const long long*)e;
        return (int)p[(dst ? E : 0) + i];
    } else {
        const int* p = (const int*)e;
        return p[(dst ? E : 0) + i];
    }
}

// ---------------------------------------------------------------------------
// Degree count (int atomics)
// ---------------------------------------------------------------------------
__global__ void zero_deg_kernel(int n) {
    int i = blockIdx.x * blockDim.x + threadIdx.x;
    if (i < n) g_deg[i] = 0;
}

__global__ void count_deg_kernel(const void* __restrict__ e, int E) {
    int i = blockIdx.x * blockDim.x + threadIdx.x;
    if (i >= E) return;
    atomicAdd(&g_deg[load_idx(e, i, E, true)], 1);
}

// ---------------------------------------------------------------------------
// Single-block scan: exclusive prefix (g_off, g_cursor) + dinv = rsqrt(deg+1)
// ---------------------------------------------------------------------------
#define SCAN_T 1024
__global__ void scan_kernel(int N) {
    __shared__ int sdata[SCAN_T];
    int tid = threadIdx.x;
    int CH = (N + SCAN_T - 1) / SCAN_T;
    int c0 = tid * CH;
    int c1 = min(c0 + CH, N);
    int s = 0;
    for (int i = c0; i < c1; i++) s += g_deg[i];
    sdata[tid] = s;
    __syncthreads();
    for (int off = 1; off < SCAN_T; off <<= 1) {
        int v = sdata[tid];
        int add = (tid >= off) ? sdata[tid - off] : 0;
        __syncthreads();
        sdata[tid] = v + add;
        __syncthreads();
    }
    int run = (tid == 0) ? 0 : sdata[tid - 1];
    for (int i = c0; i < c1; i++) {
        int d = g_deg[i];
        g_off[i] = run;
        g_cursor[i] = run;
        g_dinv[i] = rsqrtf((float)(d + 1));
        run += d;
    }
    if (tid == 0) g_off[N] = sdata[SCAN_T - 1];
}

// ---------------------------------------------------------------------------
// CSR fill (incoming-edge lists): order within a bucket is nondeterministic,
// but fp-sum ordering tolerance is covered by the 1e-3 rel-err check (the
// previous atomic version had the same property and passed revalidation).
// ---------------------------------------------------------------------------
__global__ void fill_kernel(const void* __restrict__ e, int E) {
    int i = blockIdx.x * blockDim.x + threadIdx.x;
    if (i >= E) return;
    int s = load_idx(e, i, E, false);
    int d = load_idx(e, i, E, true);
    int pos = atomicAdd(&g_cursor[d], 1);
    g_srcs[pos] = s;
}

// ---------------------------------------------------------------------------
// bf16 split-precision tensor GEMM: y[r][c] = dinv[r] * sum_k x[r][k]*W[k][c]
// x = xh + xl (bf16 hi/lo), W = Wh + Wl; acc = xh*Wh + xh*Wl + xl*Wh (fp32 acc)
// Tile: BM=128, BN=64, BK=32. 8 warps (4 along M x 2 along N), warp tile 32x32.
// ---------------------------------------------------------------------------
#define BM 128
#define BN 64
#define BK 32
#define KPAD 36

__device__ __forceinline__ void split_bf16(float v, __nv_bfloat16& h, __nv_bfloat16& l) {
    h = __float2bfloat16(v);
    l = __float2bfloat16(v - __bfloat162float(h));
}

__device__ __forceinline__ uint32_t pack2(__nv_bfloat16 lo, __nv_bfloat16 hi) {
    __nv_bfloat162 t = __halves2bfloat162(lo, hi);
    return *(uint32_t*)&t;
}

#define MMA_BF16(d, a, b)                                                      \
    asm volatile(                                                              \
        "mma.sync.aligned.m16n8k16.row.col.f32.bf16.bf16.f32 "                 \
        "{%0,%1,%2,%3}, {%4,%5,%6,%7}, {%8,%9}, {%0,%1,%2,%3};\n"              \
        : "+f"(d[0]), "+f"(d[1]), "+f"(d[2]), "+f"(d[3])                       \
        : "r"(a[0]), "r"(a[1]), "r"(a[2]), "r"(a[3]), "r"(b[0]), "r"(b[1]))

__global__ __launch_bounds__(256, 2) void gemm_bf16_kernel(
    const float* __restrict__ x, const float* __restrict__ W, int M)
{
    __shared__ __nv_bfloat16 Ah[BM][KPAD];
    __shared__ __nv_bfloat16 Al[BM][KPAD];
    __shared__ __nv_bfloat16 Bh[BN][KPAD];
    __shared__ __nv_bfloat16 Bl[BN][KPAD];

    const int tid = threadIdx.x;
    const int wid = tid >> 5;
    const int lane = tid & 31;
    const int g = lane >> 2;
    const int tg = lane & 3;
    const int wm = (wid & 3) * 32;   // warp m offset
    const int wn = (wid >> 2) * 32;  // warp n offset
    const int bm = blockIdx.x * BM;
    const int bn = blockIdx.y * BN;

    float acc[2][4][4];
#pragma unroll
    for (int mi = 0; mi < 2; mi++)
#pragma unroll
        for (int ni = 0; ni < 4; ni++)
#pragma unroll
            for (int c = 0; c < 4; c++) acc[mi][ni][c] = 0.0f;

    const int arow = tid >> 3;        // 0..31 (A: 128 rows x 32 k, 4 passes)
    const int acol = (tid & 7) * 4;   // 0..28
    const int wk = tid >> 4;          // 0..15 (B: 32 k x 64 n, 2 passes)
    const int wn4 = (tid & 15) * 4;   // 0..60

    for (int k0 = 0; k0 < FEAT; k0 += BK) {
        // ---- A tile: load fp32, split hi/lo into smem [m][k] ----
#pragma unroll
        for (int i = 0; i < 4; i++) {
            int r = arow + i * 32;
            float4 v = make_float4(0.f, 0.f, 0.f, 0.f);
            if (bm + r < M)
                v = *(const float4*)(x + (size_t)(bm + r) * FEAT + k0 + acol);
            __nv_bfloat16 hx, hy, hz, hw, lx, ly, lz, lw;
            split_bf16(v.x, hx, lx); split_bf16(v.y, hy, ly);
            split_bf16(v.z, hz, lz); split_bf16(v.w, hw, lw);
            uint2 ph = make_uint2(pack2(hx, hy), pack2(hz, hw));
            uint2 pl = make_uint2(pack2(lx, ly), pack2(lz, lw));
            *(uint2*)&Ah[r][acol] = ph;
            *(uint2*)&Al[r][acol] = pl;
        }
        // ---- B tile: load W[k][n] fp32, split, transpose into smem [n][k] ----
#pragma unroll
        for (int i = 0; i < 2; i++) {
            int kk = wk + i * 16;
            float4 v = *(const float4*)(W + (size_t)(k0 + kk) * FEAT + bn + wn4);
            float vv[4] = {v.x, v.y, v.z, v.w};
#pragma unroll
            for (int c = 0; c < 4; c++) {
                __nv_bfloat16 h, l;
                split_bf16(vv[c], h, l);
                Bh[wn4 + c][kk] = h;
                Bl[wn4 + c][kk] = l;
            }
        }
        __syncthreads();

#pragma unroll
        for (int ks = 0; ks < BK; ks += 16) {
            uint32_t ah[2][4], al[2][4];
#pragma unroll
            for (int mi = 0; mi < 2; mi++) {
                int r = wm + mi * 16 + g;
                ah[mi][0] = *(uint32_t*)&Ah[r][ks + 2 * tg];
                ah[mi][1] = *(uint32_t*)&Ah[r + 8][ks + 2 * tg];
                ah[mi][2] = *(uint32_t*)&Ah[r][ks + 2 * tg + 8];
                ah[mi][3] = *(uint32_t*)&Ah[r + 8][ks + 2 * tg + 8];
                al[mi][0] = *(uint32_t*)&Al[r][ks + 2 * tg];
                al[mi][1] = *(uint32_t*)&Al[r + 8][ks + 2 * tg];
                al[mi][2] = *(uint32_t*)&Al[r][ks + 2 * tg + 8];
                al[mi][3] = *(uint32_t*)&Al[r + 8][ks + 2 * tg + 8];
            }
            uint32_t bh[4][2], bl[4][2];
#pragma unroll
            for (int ni = 0; ni < 4; ni++) {
                int n = wn + ni * 8 + g;
                bh[ni][0] = *(uint32_t*)&Bh[n][ks + 2 * tg];
                bh[ni][1] = *(uint32_t*)&Bh[n][ks + 2 * tg + 8];
                bl[ni][0] = *(uint32_t*)&Bl[n][ks + 2 * tg];
                bl[ni][1] = *(uint32_t*)&Bl[n][ks + 2 * tg + 8];
            }
#pragma unroll
            for (int mi = 0; mi < 2; mi++)
#pragma unroll
                for (int ni = 0; ni < 4; ni++) {
                    MMA_BF16(acc[mi][ni], ah[mi], bh[ni]);
                    MMA_BF16(acc[mi][ni], ah[mi], bl[ni]);
                    MMA_BF16(acc[mi][ni], al[mi], bh[ni]);
                }
        }
        __syncthreads();
    }

    // epilogue: y = acc * dinv[row]
#pragma unroll
    for (int mi = 0; mi < 2; mi++) {
        int r0 = bm + wm + mi * 16 + g;
        int r1 = r0 + 8;
        float dv0 = (r0 < M) ? g_dinv[r0] : 0.0f;
        float dv1 = (r1 < M) ? g_dinv[r1] : 0.0f;
#pragma unroll
        for (int ni = 0; ni < 4; ni++) {
            int c = bn + wn + ni * 8 + 2 * tg;
            if (r0 < M) {
                float2 o = make_float2(acc[mi][ni][0] * dv0, acc[mi][ni][1] * dv0);
                *(float2*)(g_y + (size_t)r0 * FEAT + c) = o;
            }
            if (r1 < M) {
                float2 o = make_float2(acc[mi][ni][2] * dv1, acc[mi][ni][3] * dv1);
                *(float2*)(g_y + (size_t)r1 * FEAT + c) = o;
            }
        }
    }
}

// ---------------------------------------------------------------------------
// Pull aggregation: one warp per dst node.
// out[d] = relu(dinv[d] * (y[d] + sum_{s in N(d)} y[s]) + b)
// Each output row is written exactly once (no atomics).
// ---------------------------------------------------------------------------
__global__ __launch_bounds__(256) void pull_kernel(
    float* __restrict__ out, const float* __restrict__ bias, int N)
{
    int warp = (blockIdx.x * blockDim.x + threadIdx.x) >> 5;
    int lane = threadIdx.x & 31;
    if (warp >= N) return;

    int beg = g_off[warp];
    int end = g_off[warp + 1];
    float dv = g_dinv[warp];

    const float4* yself = (const float4*)(g_y + (size_t)warp * FEAT);
    float4 a0 = yself[lane];
    float4 a1 = yself[lane + 32];

    int j = beg;
    // 2x unrolled gather for MLP
    for (; j + 2 <= end; j += 2) {
        int s0 = g_srcs[j];
        int s1 = g_srcs[j + 1];
        const float4* y0 = (const float4*)(g_y + (size_t)s0 * FEAT);
        const float4* y1 = (const float4*)(g_y + (size_t)s1 * FEAT);
        float4 v00 = y0[lane], v01 = y0[lane + 32];
        float4 v10 = y1[lane], v11 = y1[lane + 32];
        a0.x += v00.x + v10.x; a0.y += v00.y + v10.y;
        a0.z += v00.z + v10.z; a0.w += v00.w + v10.w;
        a1.x += v01.x + v11.x; a1.y += v01.y + v11.y;
        a1.z += v01.z + v11.z; a1.w += v01.w + v11.w;
    }
    if (j < end) {
        int s0 = g_srcs[j];
        const float4* y0 = (const float4*)(g_y + (size_t)s0 * FEAT);
        float4 v00 = y0[lane], v01 = y0[lane + 32];
        a0.x += v00.x; a0.y += v00.y; a0.z += v00.z; a0.w += v00.w;
        a1.x += v01.x; a1.y += v01.y; a1.z += v01.z; a1.w += v01.w;
    }

    float4 b0 = ((const float4*)bias)[lane];
    float4 b1 = ((const float4*)bias)[lane + 32];
    float4 o0, o1;
    o0.x = fmaxf(fmaf(a0.x, dv, b0.x), 0.f);
    o0.y = fmaxf(fmaf(a0.y, dv, b0.y), 0.f);
    o0.z = fmaxf(fmaf(a0.z, dv, b0.z), 0.f);
    o0.w = fmaxf(fmaf(a0.w, dv, b0.w), 0.f);
    o1.x = fmaxf(fmaf(a1.x, dv, b1.x), 0.f);
    o1.y = fmaxf(fmaf(a1.y, dv, b1.y), 0.f);
    o1.z = fmaxf(fmaf(a1.z, dv, b1.z), 0.f);
    o1.w = fmaxf(fmaf(a1.w, dv, b1.w), 0.f);

    float4* orow = (float4*)(out + (size_t)warp * FEAT);
    orow[lane] = o0;
    orow[lane + 32] = o1;
}

// ---------------------------------------------------------------------------
// Launch
// ---------------------------------------------------------------------------
extern "C" void kernel_launch(void* const* d_in, const int* in_sizes, int n_in,
                              void* d_out, int out_size)
{
    const float* x = (const float*)d_in[0];
    const void*  e = d_in[1];
    const float* W = (const float*)d_in[2];
    const float* b = (const float*)d_in[3];
    float* out = (float*)d_out;

    const int N = in_sizes[0] / FEAT;   // 50000
    const int E = in_sizes[1] / 2;      // 1,600,000 (element count is dtype-agnostic)

    detect_dtype_kernel<<<1, 256>>>((const int*)e);
    zero_deg_kernel<<<(N + 255) / 256, 256>>>(N);
    count_deg_kernel<<<(E + 255) / 256, 256>>>(e, E);
    scan_kernel<<<1, SCAN_T>>>(N);
    fill_kernel<<<(E + 255) / 256, 256>>>(e, E);

    dim3 ggrid((N + BM - 1) / BM, FEAT / BN);
    gemm_bf16_kernel<<<ggrid, 256>>>(x, W, N);

    int pblocks = (N + 7) / 8;  // 8 warps per 256-thread block
    pull_kernel<<<pblocks, 256>>>(out, b, N);
}

// round 5
// speedup vs baseline: 1.9742x; 1.3947x over previous
#include <cuda_runtime.h>
#include <cuda_bf16.h>
#include <stdint.h>

#define FEAT 256
#define N_MAXN 50176
#define E_MAXE 1605632

// ---------------- device scratch (static; no allocation allowed) ------------
__device__ float g_y[(size_t)N_MAXN * FEAT];     // xw * dinv[row]
__device__ int   g_deg[N_MAXN];
__device__ float g_dinv[N_MAXN];
__device__ int   g_off[N_MAXN + 1];
__device__ int   g_cursor[N_MAXN];
__device__ int   g_srcs[E_MAXE];
__device__ int   g_bsum[128];
__device__ int   g_bpre[128];
__device__ int   g_is64;

// ---------------------------------------------------------------------------
// Edge-index dtype probe (int64 per reference, but JAX may emit int32).
// If int64 with values < 2^31, every high word is 0. Deterministic.
// ---------------------------------------------------------------------------
__global__ void detect_dtype_kernel(const int* __restrict__ e) {
    __shared__ int any_nonzero;
    if (threadIdx.x == 0) any_nonzero = 0;
    __syncthreads();
    int local = 0;
    for (int i = threadIdx.x; i < 512; i += blockDim.x)
        if (e[2 * i + 1] != 0) local = 1;
    if (local) atomicExch(&any_nonzero, 1);
    __syncthreads();
    if (threadIdx.x == 0) g_is64 = any_nonzero ? 0 : 1;
}

__device__ __forceinline__ int load_idx(const void* e, long long i, long long E, bool dst) {
    if (g_is64) {
        const long long* p = (const long long*)e;
        return (int)p[(dst ? E : 0) + i];
    } else {
        const int* p = (const int*)e;
        return p[(dst ? E : 0) + i];
    }
}

// ---------------------------------------------------------------------------
// Degree count (int atomics)
// ---------------------------------------------------------------------------
__global__ void zero_deg_kernel(int n) {
    int i = blockIdx.x * blockDim.x + threadIdx.x;
    if (i < n) g_deg[i] = 0;
}

__global__ void count_deg_kernel(const void* __restrict__ e, int E) {
    int i = blockIdx.x * blockDim.x + threadIdx.x;
    if (i >= E) return;
    atomicAdd(&g_deg[load_idx(e, i, E, true)], 1);
}

// ---------------------------------------------------------------------------
// Three-level parallel exclusive scan of g_deg (replaces 103us 1-block scan).
// Level 1: per-512-chunk sums (full-chip). Level 2: scan 98 partials (1 blk).
// Level 3: per-chunk shared scan + block prefix; writes off/cursor/dinv.
// ---------------------------------------------------------------------------
#define SCB 512

__global__ __launch_bounds__(SCB) void block_sum_kernel(int N) {
    __shared__ int sd[SCB];
    int t = threadIdx.x;
    int i = blockIdx.x * SCB + t;
    sd[t] = (i < N) ? g_deg[i] : 0;
    __syncthreads();
#pragma unroll
    for (int off = SCB / 2; off > 0; off >>= 1) {
        if (t < off) sd[t] += sd[t + off];
        __syncthreads();
    }
    if (t == 0) g_bsum[blockIdx.x] = sd[0];
}

__global__ __launch_bounds__(128) void scan_bsum_kernel(int NB) {
    __shared__ int sd[128];
    int t = threadIdx.x;
    sd[t] = (t < NB) ? g_bsum[t] : 0;
    __syncthreads();
#pragma unroll
    for (int off = 1; off < 128; off <<= 1) {
        int v = sd[t];
        int a = (t >= off) ? sd[t - off] : 0;
        __syncthreads();
        sd[t] = v + a;
        __syncthreads();
    }
    if (t < NB) g_bpre[t] = (t == 0) ? 0 : sd[t - 1];
}

__global__ __launch_bounds__(SCB) void scan_final_kernel(int N) {
    __shared__ int sd[SCB];
    int t = threadIdx.x;
    int i = blockIdx.x * SCB + t;
    int d = (i < N) ? g_deg[i] : 0;
    sd[t] = d;
    __syncthreads();
#pragma unroll
    for (int off = 1; off < SCB; off <<= 1) {
        int v = sd[t];
        int a = (t >= off) ? sd[t - off] : 0;
        __syncthreads();
        sd[t] = v + a;
        __syncthreads();
    }
    if (i < N) {
        int excl = sd[t] - d + g_bpre[blockIdx.x];
        g_off[i] = excl;
        g_cursor[i] = excl;
        g_dinv[i] = rsqrtf((float)(d + 1));
        if (i == N - 1) g_off[N] = excl + d;
    }
}

// ---------------------------------------------------------------------------
// CSR fill (incoming-edge lists): order within a bucket is nondeterministic,
// but fp-sum ordering tolerance is covered by the 1e-3 rel-err check.
// ---------------------------------------------------------------------------
__global__ void fill_kernel(const void* __restrict__ e, int E) {
    int i = blockIdx.x * blockDim.x + threadIdx.x;
    if (i >= E) return;
    int s = load_idx(e, i, E, false);
    int d = load_idx(e, i, E, true);
    int pos = atomicAdd(&g_cursor[d], 1);
    g_srcs[pos] = s;
}

// ---------------------------------------------------------------------------
// bf16 split-precision tensor GEMM: y[r][c] = dinv[r] * sum_k x[r][k]*W[k][c]
// x = xh + xl (bf16 hi/lo), W = Wh + Wl; acc = xh*Wh + xh*Wl + xl*Wh (fp32 acc)
// Tile: BM=128, BN=64, BK=32. 8 warps (4 along M x 2 along N), warp tile 32x32.
// ---------------------------------------------------------------------------
#define BM 128
#define BN 64
#define BK 32
#define KPAD 36

__device__ __forceinline__ void split_bf16(float v, __nv_bfloat16& h, __nv_bfloat16& l) {
    h = __float2bfloat16(v);
    l = __float2bfloat16(v - __bfloat162float(h));
}

__device__ __forceinline__ uint32_t pack2(__nv_bfloat16 lo, __nv_bfloat16 hi) {
    __nv_bfloat162 t = __halves2bfloat162(lo, hi);
    return *(uint32_t*)&t;
}

#define MMA_BF16(d, a, b)                                                      \
    asm volatile(                                                              \
        "mma.sync.aligned.m16n8k16.row.col.f32.bf16.bf16.f32 "                 \
        "{%0,%1,%2,%3}, {%4,%5,%6,%7}, {%8,%9}, {%0,%1,%2,%3};\n"              \
        : "+f"(d[0]), "+f"(d[1]), "+f"(d[2]), "+f"(d[3])                       \
        : "r"(a[0]), "r"(a[1]), "r"(a[2]), "r"(a[3]), "r"(b[0]), "r"(b[1]))

__global__ __launch_bounds__(256, 2) void gemm_bf16_kernel(
    const float* __restrict__ x, const float* __restrict__ W, int M)
{
    __shared__ __nv_bfloat16 Ah[BM][KPAD];
    __shared__ __nv_bfloat16 Al[BM][KPAD];
    __shared__ __nv_bfloat16 Bh[BN][KPAD];
    __shared__ __nv_bfloat16 Bl[BN][KPAD];

    const int tid = threadIdx.x;
    const int wid = tid >> 5;
    const int lane = tid & 31;
    const int g = lane >> 2;
    const int tg = lane & 3;
    const int wm = (wid & 3) * 32;   // warp m offset
    const int wn = (wid >> 2) * 32;  // warp n offset
    const int bm = blockIdx.x * BM;
    const int bn = blockIdx.y * BN;

    float acc[2][4][4];
#pragma unroll
    for (int mi = 0; mi < 2; mi++)
#pragma unroll
        for (int ni = 0; ni < 4; ni++)
#pragma unroll
            for (int c = 0; c < 4; c++) acc[mi][ni][c] = 0.0f;

    const int arow = tid >> 3;        // 0..31 (A: 128 rows x 32 k, 4 passes)
    const int acol = (tid & 7) * 4;   // 0..28
    const int wk = tid >> 4;          // 0..15 (B: 32 k x 64 n, 2 passes)
    const int wn4 = (tid & 15) * 4;   // 0..60

    for (int k0 = 0; k0 < FEAT; k0 += BK) {
        // ---- A tile: load fp32, split hi/lo into smem [m][k] ----
#pragma unroll
        for (int i = 0; i < 4; i++) {
            int r = arow + i * 32;
            float4 v = make_float4(0.f, 0.f, 0.f, 0.f);
            if (bm + r < M)
                v = *(const float4*)(x + (size_t)(bm + r) * FEAT + k0 + acol);
            __nv_bfloat16 hx, hy, hz, hw, lx, ly, lz, lw;
            split_bf16(v.x, hx, lx); split_bf16(v.y, hy, ly);
            split_bf16(v.z, hz, lz); split_bf16(v.w, hw, lw);
            uint2 ph = make_uint2(pack2(hx, hy), pack2(hz, hw));
            uint2 pl = make_uint2(pack2(lx, ly), pack2(lz, lw));
            *(uint2*)&Ah[r][acol] = ph;
            *(uint2*)&Al[r][acol] = pl;
        }
        // ---- B tile: load W[k][n] fp32, split, transpose into smem [n][k] ----
#pragma unroll
        for (int i = 0; i < 2; i++) {
            int kk = wk + i * 16;
            float4 v = *(const float4*)(W + (size_t)(k0 + kk) * FEAT + bn + wn4);
            float vv[4] = {v.x, v.y, v.z, v.w};
#pragma unroll
            for (int c = 0; c < 4; c++) {
                __nv_bfloat16 h, l;
                split_bf16(vv[c], h, l);
                Bh[wn4 + c][kk] = h;
                Bl[wn4 + c][kk] = l;
            }
        }
        __syncthreads();

#pragma unroll
        for (int ks = 0; ks < BK; ks += 16) {
            uint32_t ah[2][4], al[2][4];
#pragma unroll
            for (int mi = 0; mi < 2; mi++) {
                int r = wm + mi * 16 + g;
                ah[mi][0] = *(uint32_t*)&Ah[r][ks + 2 * tg];
                ah[mi][1] = *(uint32_t*)&Ah[r + 8][ks + 2 * tg];
                ah[mi][2] = *(uint32_t*)&Ah[r][ks + 2 * tg + 8];
                ah[mi][3] = *(uint32_t*)&Ah[r + 8][ks + 2 * tg + 8];
                al[mi][0] = *(uint32_t*)&Al[r][ks + 2 * tg];
                al[mi][1] = *(uint32_t*)&Al[r + 8][ks + 2 * tg];
                al[mi][2] = *(uint32_t*)&Al[r][ks + 2 * tg + 8];
                al[mi][3] = *(uint32_t*)&Al[r + 8][ks + 2 * tg + 8];
            }
            uint32_t bh[4][2], bl[4][2];
#pragma unroll
            for (int ni = 0; ni < 4; ni++) {
                int n = wn + ni * 8 + g;
                bh[ni][0] = *(uint32_t*)&Bh[n][ks + 2 * tg];
                bh[ni][1] = *(uint32_t*)&Bh[n][ks + 2 * tg + 8];
                bl[ni][0] = *(uint32_t*)&Bl[n][ks + 2 * tg];
                bl[ni][1] = *(uint32_t*)&Bl[n][ks + 2 * tg + 8];
            }
#pragma unroll
            for (int mi = 0; mi < 2; mi++)
#pragma unroll
                for (int ni = 0; ni < 4; ni++) {
                    MMA_BF16(acc[mi][ni], ah[mi], bh[ni]);
                    MMA_BF16(acc[mi][ni], ah[mi], bl[ni]);
                    MMA_BF16(acc[mi][ni], al[mi], bh[ni]);
                }
        }
        __syncthreads();
    }

    // epilogue: y = acc * dinv[row]
#pragma unroll
    for (int mi = 0; mi < 2; mi++) {
        int r0 = bm + wm + mi * 16 + g;
        int r1 = r0 + 8;
        float dv0 = (r0 < M) ? g_dinv[r0] : 0.0f;
        float dv1 = (r1 < M) ? g_dinv[r1] : 0.0f;
#pragma unroll
        for (int ni = 0; ni < 4; ni++) {
            int c = bn + wn + ni * 8 + 2 * tg;
            if (r0 < M) {
                float2 o = make_float2(acc[mi][ni][0] * dv0, acc[mi][ni][1] * dv0);
                *(float2*)(g_y + (size_t)r0 * FEAT + c) = o;
            }
            if (r1 < M) {
                float2 o = make_float2(acc[mi][ni][2] * dv1, acc[mi][ni][3] * dv1);
                *(float2*)(g_y + (size_t)r1 * FEAT + c) = o;
            }
        }
    }
}

// ---------------------------------------------------------------------------
// Pull aggregation: one warp per dst node.
// out[d] = relu(dinv[d] * (y[d] + sum_{s in N(d)} y[s]) + b)
// Each output row is written exactly once (no atomics).
// ---------------------------------------------------------------------------
__global__ __launch_bounds__(256) void pull_kernel(
    float* __restrict__ out, const float* __restrict__ bias, int N)
{
    int warp = (blockIdx.x * blockDim.x + threadIdx.x) >> 5;
    int lane = threadIdx.x & 31;
    if (warp >= N) return;

    int beg = g_off[warp];
    int end = g_off[warp + 1];
    float dv = g_dinv[warp];

    const float4* yself = (const float4*)(g_y + (size_t)warp * FEAT);
    float4 a0 = yself[lane];
    float4 a1 = yself[lane + 32];

    int j = beg;
    // 2x unrolled gather for MLP
    for (; j + 2 <= end; j += 2) {
        int s0 = g_srcs[j];
        int s1 = g_srcs[j + 1];
        const float4* y0 = (const float4*)(g_y + (size_t)s0 * FEAT);
        const float4* y1 = (const float4*)(g_y + (size_t)s1 * FEAT);
        float4 v00 = y0[lane], v01 = y0[lane + 32];
        float4 v10 = y1[lane], v11 = y1[lane + 32];
        a0.x += v00.x + v10.x; a0.y += v00.y + v10.y;
        a0.z += v00.z + v10.z; a0.w += v00.w + v10.w;
        a1.x += v01.x + v11.x; a1.y += v01.y + v11.y;
        a1.z += v01.z + v11.z; a1.w += v01.w + v11.w;
    }
    if (j < end) {
        int s0 = g_srcs[j];
        const float4* y0 = (const float4*)(g_y + (size_t)s0 * FEAT);
        float4 v00 = y0[lane], v01 = y0[lane + 32];
        a0.x += v00.x; a0.y += v00.y; a0.z += v00.z; a0.w += v00.w;
        a1.x += v01.x; a1.y += v01.y; a1.z += v01.z; a1.w += v01.w;
    }

    float4 b0 = ((const float4*)bias)[lane];
    float4 b1 = ((const float4*)bias)[lane + 32];
    float4 o0, o1;
    o0.x = fmaxf(fmaf(a0.x, dv, b0.x), 0.f);
    o0.y = fmaxf(fmaf(a0.y, dv, b0.y), 0.f);
    o0.z = fmaxf(fmaf(a0.z, dv, b0.z), 0.f);
    o0.w = fmaxf(fmaf(a0.w, dv, b0.w), 0.f);
    o1.x = fmaxf(fmaf(a1.x, dv, b1.x), 0.f);
    o1.y = fmaxf(fmaf(a1.y, dv, b1.y), 0.f);
    o1.z = fmaxf(fmaf(a1.z, dv, b1.z), 0.f);
    o1.w = fmaxf(fmaf(a1.w, dv, b1.w), 0.f);

    float4* orow = (float4*)(out + (size_t)warp * FEAT);
    orow[lane] = o0;
    orow[lane + 32] = o1;
}

// ---------------------------------------------------------------------------
// Launch
// ---------------------------------------------------------------------------
extern "C" void kernel_launch(void* const* d_in, const int* in_sizes, int n_in,
                              void* d_out, int out_size)
{
    const float* x = (const float*)d_in[0];
    const void*  e = d_in[1];
    const float* W = (const float*)d_in[2];
    const float* b = (const float*)d_in[3];
    float* out = (float*)d_out;

    const int N = in_sizes[0] / FEAT;   // 50000
    const int E = in_sizes[1] / 2;      // 1,600,000

    detect_dtype_kernel<<<1, 256>>>((const int*)e);
    zero_deg_kernel<<<(N + 255) / 256, 256>>>(N);
    count_deg_kernel<<<(E + 255) / 256, 256>>>(e, E);

    int NB = (N + SCB - 1) / SCB;  // 98 for N=50000
    block_sum_kernel<<<NB, SCB>>>(N);
    scan_bsum_kernel<<<1, 128>>>(NB);
    scan_final_kernel<<<NB, SCB>>>(N);

    fill_kernel<<<(E + 255) / 256, 256>>>(e, E);

    dim3 ggrid((N + BM - 1) / BM, FEAT / BN);
    gemm_bf16_kernel<<<ggrid, 256>>>(x, W, N);

    int pblocks = (N + 7) / 8;  // 8 warps per 256-thread block
    pull_kernel<<<pblocks, 256>>>(out, b, N);
}

// round 6
// speedup vs baseline: 2.2339x; 1.1315x over previous
#include <cuda_runtime.h>
#include <cuda_bf16.h>
#include <cuda_fp16.h>
#include <stdint.h>

#define FEAT 256
#define N_MAXN 50176
#define E_MAXE 1605632

// ---------------- device scratch (static; no allocation allowed) ------------
__device__ __half g_yh[(size_t)N_MAXN * FEAT];   // fp16: xw * dinv[row]
__device__ int   g_deg[N_MAXN];
__device__ float g_dinv[N_MAXN];
__device__ int   g_off[N_MAXN + 1];
__device__ int   g_cursor[N_MAXN];
__device__ int   g_srcs[E_MAXE];
__device__ int   g_bsum[128];
__device__ int   g_bpre[128];
__device__ int   g_is64;

// ---------------------------------------------------------------------------
// Edge-index dtype probe (int64 per reference, but JAX may emit int32).
// ---------------------------------------------------------------------------
__global__ void detect_dtype_kernel(const int* __restrict__ e) {
    __shared__ int any_nonzero;
    if (threadIdx.x == 0) any_nonzero = 0;
    __syncthreads();
    int local = 0;
    for (int i = threadIdx.x; i < 512; i += blockDim.x)
        if (e[2 * i + 1] != 0) local = 1;
    if (local) atomicExch(&any_nonzero, 1);
    __syncthreads();
    if (threadIdx.x == 0) g_is64 = any_nonzero ? 0 : 1;
}

__device__ __forceinline__ int load_idx(const void* e, long long i, long long E, bool dst) {
    if (g_is64) {
        const long long* p = (const long long*)e;
        return (int)p[(dst ? E : 0) + i];
    } else {
        const int* p = (const int*)e;
        return p[(dst ? E : 0) + i];
    }
}

// ---------------------------------------------------------------------------
// Degree count
// ---------------------------------------------------------------------------
__global__ void zero_deg_kernel(int n) {
    int i = blockIdx.x * blockDim.x + threadIdx.x;
    if (i < n) g_deg[i] = 0;
}

__global__ void count_deg_kernel(const void* __restrict__ e, int E) {
    int i = blockIdx.x * blockDim.x + threadIdx.x;
    if (i >= E) return;
    atomicAdd(&g_deg[load_idx(e, i, E, true)], 1);
}

// ---------------------------------------------------------------------------
// Three-level parallel exclusive scan of g_deg
// ---------------------------------------------------------------------------
#define SCB 512

__global__ __launch_bounds__(SCB) void block_sum_kernel(int N) {
    __shared__ int sd[SCB];
    int t = threadIdx.x;
    int i = blockIdx.x * SCB + t;
    sd[t] = (i < N) ? g_deg[i] : 0;
    __syncthreads();
#pragma unroll
    for (int off = SCB / 2; off > 0; off >>= 1) {
        if (t < off) sd[t] += sd[t + off];
        __syncthreads();
    }
    if (t == 0) g_bsum[blockIdx.x] = sd[0];
}

__global__ __launch_bounds__(128) void scan_bsum_kernel(int NB) {
    __shared__ int sd[128];
    int t = threadIdx.x;
    sd[t] = (t < NB) ? g_bsum[t] : 0;
    __syncthreads();
#pragma unroll
    for (int off = 1; off < 128; off <<= 1) {
        int v = sd[t];
        int a = (t >= off) ? sd[t - off] : 0;
        __syncthreads();
        sd[t] = v + a;
        __syncthreads();
    }
    if (t < NB) g_bpre[t] = (t == 0) ? 0 : sd[t - 1];
}

__global__ __launch_bounds__(SCB) void scan_final_kernel(int N) {
    __shared__ int sd[SCB];
    int t = threadIdx.x;
    int i = blockIdx.x * SCB + t;
    int d = (i < N) ? g_deg[i] : 0;
    sd[t] = d;
    __syncthreads();
#pragma unroll
    for (int off = 1; off < SCB; off <<= 1) {
        int v = sd[t];
        int a = (t >= off) ? sd[t - off] : 0;
        __syncthreads();
        sd[t] = v + a;
        __syncthreads();
    }
    if (i < N) {
        int excl = sd[t] - d + g_bpre[blockIdx.x];
        g_off[i] = excl;
        g_cursor[i] = excl;
        g_dinv[i] = rsqrtf((float)(d + 1));
        if (i == N - 1) g_off[N] = excl + d;
    }
}

// ---------------------------------------------------------------------------
// CSR fill (incoming-edge lists)
// ---------------------------------------------------------------------------
__global__ void fill_kernel(const void* __restrict__ e, int E) {
    int i = blockIdx.x * blockDim.x + threadIdx.x;
    if (i >= E) return;
    int s = load_idx(e, i, E, false);
    int d = load_idx(e, i, E, true);
    int pos = atomicAdd(&g_cursor[d], 1);
    g_srcs[pos] = s;
}

// ---------------------------------------------------------------------------
// bf16 split-precision tensor GEMM: y[r][c] = dinv[r] * sum_k x[r][k]*W[k][c]
// Epilogue stores y as fp16 (halves pull-gather traffic).
// ---------------------------------------------------------------------------
#define BM 128
#define BN 64
#define BK 32
#define KPAD 36

__device__ __forceinline__ void split_bf16(float v, __nv_bfloat16& h, __nv_bfloat16& l) {
    h = __float2bfloat16(v);
    l = __float2bfloat16(v - __bfloat162float(h));
}

__device__ __forceinline__ uint32_t pack2(__nv_bfloat16 lo, __nv_bfloat16 hi) {
    __nv_bfloat162 t = __halves2bfloat162(lo, hi);
    return *(uint32_t*)&t;
}

#define MMA_BF16(d, a, b)                                                      \
    asm volatile(                                                              \
        "mma.sync.aligned.m16n8k16.row.col.f32.bf16.bf16.f32 "                 \
        "{%0,%1,%2,%3}, {%4,%5,%6,%7}, {%8,%9}, {%0,%1,%2,%3};\n"              \
        : "+f"(d[0]), "+f"(d[1]), "+f"(d[2]), "+f"(d[3])                       \
        : "r"(a[0]), "r"(a[1]), "r"(a[2]), "r"(a[3]), "r"(b[0]), "r"(b[1]))

__global__ __launch_bounds__(256, 2) void gemm_bf16_kernel(
    const float* __restrict__ x, const float* __restrict__ W, int M)
{
    __shared__ __nv_bfloat16 Ah[BM][KPAD];
    __shared__ __nv_bfloat16 Al[BM][KPAD];
    __shared__ __nv_bfloat16 Bh[BN][KPAD];
    __shared__ __nv_bfloat16 Bl[BN][KPAD];

    const int tid = threadIdx.x;
    const int wid = tid >> 5;
    const int lane = tid & 31;
    const int g = lane >> 2;
    const int tg = lane & 3;
    const int wm = (wid & 3) * 32;
    const int wn = (wid >> 2) * 32;
    const int bm = blockIdx.x * BM;
    const int bn = blockIdx.y * BN;

    float acc[2][4][4];
#pragma unroll
    for (int mi = 0; mi < 2; mi++)
#pragma unroll
        for (int ni = 0; ni < 4; ni++)
#pragma unroll
            for (int c = 0; c < 4; c++) acc[mi][ni][c] = 0.0f;

    const int arow = tid >> 3;
    const int acol = (tid & 7) * 4;
    const int wk = tid >> 4;
    const int wn4 = (tid & 15) * 4;

    for (int k0 = 0; k0 < FEAT; k0 += BK) {
#pragma unroll
        for (int i = 0; i < 4; i++) {
            int r = arow + i * 32;
            float4 v = make_float4(0.f, 0.f, 0.f, 0.f);
            if (bm + r < M)
                v = *(const float4*)(x + (size_t)(bm + r) * FEAT + k0 + acol);
            __nv_bfloat16 hx, hy, hz, hw, lx, ly, lz, lw;
            split_bf16(v.x, hx, lx); split_bf16(v.y, hy, ly);
            split_bf16(v.z, hz, lz); split_bf16(v.w, hw, lw);
            *(uint2*)&Ah[r][acol] = make_uint2(pack2(hx, hy), pack2(hz, hw));
            *(uint2*)&Al[r][acol] = make_uint2(pack2(lx, ly), pack2(lz, lw));
        }
#pragma unroll
        for (int i = 0; i < 2; i++) {
            int kk = wk + i * 16;
            float4 v = *(const float4*)(W + (size_t)(k0 + kk) * FEAT + bn + wn4);
            float vv[4] = {v.x, v.y, v.z, v.w};
#pragma unroll
            for (int c = 0; c < 4; c++) {
                __nv_bfloat16 h, l;
                split_bf16(vv[c], h, l);
                Bh[wn4 + c][kk] = h;
                Bl[wn4 + c][kk] = l;
            }
        }
        __syncthreads();

#pragma unroll
        for (int ks = 0; ks < BK; ks += 16) {
            uint32_t ah[2][4], al[2][4];
#pragma unroll
            for (int mi = 0; mi < 2; mi++) {
                int r = wm + mi * 16 + g;
                ah[mi][0] = *(uint32_t*)&Ah[r][ks + 2 * tg];
                ah[mi][1] = *(uint32_t*)&Ah[r + 8][ks + 2 * tg];
                ah[mi][2] = *(uint32_t*)&Ah[r][ks + 2 * tg + 8];
                ah[mi][3] = *(uint32_t*)&Ah[r + 8][ks + 2 * tg + 8];
                al[mi][0] = *(uint32_t*)&Al[r][ks + 2 * tg];
                al[mi][1] = *(uint32_t*)&Al[r + 8][ks + 2 * tg];
                al[mi][2] = *(uint32_t*)&Al[r][ks + 2 * tg + 8];
                al[mi][3] = *(uint32_t*)&Al[r + 8][ks + 2 * tg + 8];
            }
            uint32_t bh[4][2], bl[4][2];
#pragma unroll
            for (int ni = 0; ni < 4; ni++) {
                int n = wn + ni * 8 + g;
                bh[ni][0] = *(uint32_t*)&Bh[n][ks + 2 * tg];
                bh[ni][1] = *(uint32_t*)&Bh[n][ks + 2 * tg + 8];
                bl[ni][0] = *(uint32_t*)&Bl[n][ks + 2 * tg];
                bl[ni][1] = *(uint32_t*)&Bl[n][ks + 2 * tg + 8];
            }
#pragma unroll
            for (int mi = 0; mi < 2; mi++)
#pragma unroll
                for (int ni = 0; ni < 4; ni++) {
                    MMA_BF16(acc[mi][ni], ah[mi], bh[ni]);
                    MMA_BF16(acc[mi][ni], ah[mi], bl[ni]);
                    MMA_BF16(acc[mi][ni], al[mi], bh[ni]);
                }
        }
        __syncthreads();
    }

    // epilogue: y = acc * dinv[row], stored fp16
    __half2* yh2 = (__half2*)g_yh;
#pragma unroll
    for (int mi = 0; mi < 2; mi++) {
        int r0 = bm + wm + mi * 16 + g;
        int r1 = r0 + 8;
        float dv0 = (r0 < M) ? g_dinv[r0] : 0.0f;
        float dv1 = (r1 < M) ? g_dinv[r1] : 0.0f;
#pragma unroll
        for (int ni = 0; ni < 4; ni++) {
            int c = bn + wn + ni * 8 + 2 * tg;   // even
            if (r0 < M) {
                float2 o = make_float2(acc[mi][ni][0] * dv0, acc[mi][ni][1] * dv0);
                yh2[(size_t)r0 * (FEAT / 2) + (c >> 1)] = __float22half2_rn(o);
            }
            if (r1 < M) {
                float2 o = make_float2(acc[mi][ni][2] * dv1, acc[mi][ni][3] * dv1);
                yh2[(size_t)r1 * (FEAT / 2) + (c >> 1)] = __float22half2_rn(o);
            }
        }
    }
}

// ---------------------------------------------------------------------------
// Pull aggregation: one warp per dst node, fp16 rows (512 B), one LDG.128
// per lane covers the whole row share. fp32 accumulation.
// ---------------------------------------------------------------------------
__device__ __forceinline__ void acc_row(float* acc, uint4 u) {
    __half2* h = (__half2*)&u;
#pragma unroll
    for (int q = 0; q < 4; q++) {
        float2 f = __half22float2(h[q]);
        acc[2 * q] += f.x;
        acc[2 * q + 1] += f.y;
    }
}

__global__ __launch_bounds__(256) void pull_kernel(
    float* __restrict__ out, const float* __restrict__ bias, int N)
{
    int warp = (blockIdx.x * blockDim.x + threadIdx.x) >> 5;
    int lane = threadIdx.x & 31;
    if (warp >= N) return;

    int beg = g_off[warp];
    int end = g_off[warp + 1];
    float dv = g_dinv[warp];

    const uint4* yb = (const uint4*)g_yh;   // 16 uint4 per row
    float acc[8];
    {
        uint4 u = yb[(size_t)warp * 16 + lane / 2];
        // each uint4 = 8 halves covers 2 lanes? No: row = 256 halves = 32 x 8.
        (void)u;
    }
    // Correct mapping: each lane owns 8 consecutive halves = 16 bytes = 1 uint4.
    // Row has 256 halves = 512 B = 32 uint4. lane -> uint4 index `lane`.
    {
        uint4 u = ((const uint4*)(g_yh + (size_t)warp * FEAT))[lane];
        __half2* h = (__half2*)&u;
#pragma unroll
        for (int q = 0; q < 4; q++) {
            float2 f = __half22float2(h[q]);
            acc[2 * q] = f.x;
            acc[2 * q + 1] = f.y;
        }
    }

    int j = beg;
    for (; j + 4 <= end; j += 4) {
        int s0 = g_srcs[j], s1 = g_srcs[j + 1], s2 = g_srcs[j + 2], s3 = g_srcs[j + 3];
        uint4 u0 = ((const uint4*)(g_yh + (size_t)s0 * FEAT))[lane];
        uint4 u1 = ((const uint4*)(g_yh + (size_t)s1 * FEAT))[lane];
        uint4 u2 = ((const uint4*)(g_yh + (size_t)s2 * FEAT))[lane];
        uint4 u3 = ((const uint4*)(g_yh + (size_t)s3 * FEAT))[lane];
        acc_row(acc, u0); acc_row(acc, u1); acc_row(acc, u2); acc_row(acc, u3);
    }
    for (; j < end; j++) {
        int s0 = g_srcs[j];
        uint4 u0 = ((const uint4*)(g_yh + (size_t)s0 * FEAT))[lane];
        acc_row(acc, u0);
    }

    // columns lane*8 .. lane*8+7
    float4 b0 = *(const float4*)(bias + lane * 8);
    float4 b1 = *(const float4*)(bias + lane * 8 + 4);
    float4 o0, o1;
    o0.x = fmaxf(fmaf(acc[0], dv, b0.x), 0.f);
    o0.y = fmaxf(fmaf(acc[1], dv, b0.y), 0.f);
    o0.z = fmaxf(fmaf(acc[2], dv, b0.z), 0.f);
    o0.w = fmaxf(fmaf(acc[3], dv, b0.w), 0.f);
    o1.x = fmaxf(fmaf(acc[4], dv, b1.x), 0.f);
    o1.y = fmaxf(fmaf(acc[5], dv, b1.y), 0.f);
    o1.z = fmaxf(fmaf(acc[6], dv, b1.z), 0.f);
    o1.w = fmaxf(fmaf(acc[7], dv, b1.w), 0.f);

    float* orow = out + (size_t)warp * FEAT + lane * 8;
    *(float4*)orow = o0;
    *(float4*)(orow + 4) = o1;
}

// ---------------------------------------------------------------------------
// Launch
// ---------------------------------------------------------------------------
extern "C" void kernel_launch(void* const* d_in, const int* in_sizes, int n_in,
                              void* d_out, int out_size)
{
    const float* x = (const float*)d_in[0];
    const void*  e = d_in[1];
    const float* W = (const float*)d_in[2];
    const float* b = (const float*)d_in[3];
    float* out = (float*)d_out;

    const int N = in_sizes[0] / FEAT;   // 50000
    const int E = in_sizes[1] / 2;      // 1,600,000

    detect_dtype_kernel<<<1, 256>>>((const int*)e);
    zero_deg_kernel<<<(N + 255) / 256, 256>>>(N);
    count_deg_kernel<<<(E + 255) / 256, 256>>>(e, E);

    int NB = (N + SCB - 1) / SCB;
    block_sum_kernel<<<NB, SCB>>>(N);
    scan_bsum_kernel<<<1, 128>>>(NB);
    scan_final_kernel<<<NB, SCB>>>(N);

    fill_kernel<<<(E + 255) / 256, 256>>>(e, E);

    dim3 ggrid((N + BM - 1) / BM, FEAT / BN);
    gemm_bf16_kernel<<<ggrid, 256>>>(x, W, N);

    int pblocks = (N + 7) / 8;
    pull_kernel<<<pblocks, 256>>>(out, b, N);
}

// round 7
// speedup vs baseline: 2.6783x; 1.1990x over previous
#include <cuda_runtime.h>
#include <cuda_fp16.h>
#include <stdint.h>

#define FEAT 256
#define N_MAXN 50176
#define E_MAXE 1605632

// ---------------- device scratch (static; no allocation allowed) ------------
__device__ __half g_yh[(size_t)N_MAXN * FEAT];   // fp16: xw * dinv[row]
__device__ int   g_deg[N_MAXN];
__device__ float g_dinv[N_MAXN];
__device__ int   g_off[N_MAXN + 1];
__device__ int   g_cursor[N_MAXN];
__device__ int   g_srcs[E_MAXE];
__device__ int   g_bsum[128];
__device__ int   g_bpre[128];
__device__ int   g_is64;

// ---------------------------------------------------------------------------
// Edge-index dtype probe (int64 per reference, but JAX may emit int32).
// ---------------------------------------------------------------------------
__global__ void detect_dtype_kernel(const int* __restrict__ e) {
    __shared__ int any_nonzero;
    if (threadIdx.x == 0) any_nonzero = 0;
    __syncthreads();
    int local = 0;
    for (int i = threadIdx.x; i < 512; i += blockDim.x)
        if (e[2 * i + 1] != 0) local = 1;
    if (local) atomicExch(&any_nonzero, 1);
    __syncthreads();
    if (threadIdx.x == 0) g_is64 = any_nonzero ? 0 : 1;
}

__device__ __forceinline__ int load_idx(const void* e, long long i, long long E, bool dst) {
    if (g_is64) {
        const long long* p = (const long long*)e;
        return (int)p[(dst ? E : 0) + i];
    } else {
        const int* p = (const int*)e;
        return p[(dst ? E : 0) + i];
    }
}

// ---------------------------------------------------------------------------
// Degree count
// ---------------------------------------------------------------------------
__global__ void zero_deg_kernel(int n) {
    int i = blockIdx.x * blockDim.x + threadIdx.x;
    if (i < n) g_deg[i] = 0;
}

__global__ void count_deg_kernel(const void* __restrict__ e, int E) {
    int i = blockIdx.x * blockDim.x + threadIdx.x;
    if (i >= E) return;
    atomicAdd(&g_deg[load_idx(e, i, E, true)], 1);
}

// ---------------------------------------------------------------------------
// Three-level parallel exclusive scan of g_deg
// ---------------------------------------------------------------------------
#define SCB 512

__global__ __launch_bounds__(SCB) void block_sum_kernel(int N) {
    __shared__ int sd[SCB];
    int t = threadIdx.x;
    int i = blockIdx.x * SCB + t;
    sd[t] = (i < N) ? g_deg[i] : 0;
    __syncthreads();
#pragma unroll
    for (int off = SCB / 2; off > 0; off >>= 1) {
        if (t < off) sd[t] += sd[t + off];
        __syncthreads();
    }
    if (t == 0) g_bsum[blockIdx.x] = sd[0];
}

__global__ __launch_bounds__(128) void scan_bsum_kernel(int NB) {
    __shared__ int sd[128];
    int t = threadIdx.x;
    sd[t] = (t < NB) ? g_bsum[t] : 0;
    __syncthreads();
#pragma unroll
    for (int off = 1; off < 128; off <<= 1) {
        int v = sd[t];
        int a = (t >= off) ? sd[t - off] : 0;
        __syncthreads();
        sd[t] = v + a;
        __syncthreads();
    }
    if (t < NB) g_bpre[t] = (t == 0) ? 0 : sd[t - 1];
}

__global__ __launch_bounds__(SCB) void scan_final_kernel(int N) {
    __shared__ int sd[SCB];
    int t = threadIdx.x;
    int i = blockIdx.x * SCB + t;
    int d = (i < N) ? g_deg[i] : 0;
    sd[t] = d;
    __syncthreads();
#pragma unroll
    for (int off = 1; off < SCB; off <<= 1) {
        int v = sd[t];
        int a = (t >= off) ? sd[t - off] : 0;
        __syncthreads();
        sd[t] = v + a;
        __syncthreads();
    }
    if (i < N) {
        int excl = sd[t] - d + g_bpre[blockIdx.x];
        g_off[i] = excl;
        g_cursor[i] = excl;
        g_dinv[i] = rsqrtf((float)(d + 1));
        if (i == N - 1) g_off[N] = excl + d;
    }
}

// ---------------------------------------------------------------------------
// CSR fill (incoming-edge lists)
// ---------------------------------------------------------------------------
__global__ void fill_kernel(const void* __restrict__ e, int E) {
    int i = blockIdx.x * blockDim.x + threadIdx.x;
    if (i >= E) return;
    int s = load_idx(e, i, E, false);
    int d = load_idx(e, i, E, true);
    int pos = atomicAdd(&g_cursor[d], 1);
    g_srcs[pos] = s;
}

// ---------------------------------------------------------------------------
// fp16 tensor GEMM: y[r][c] = dinv[r] * sum_k x[r][k]*W[k][c], fp32 accum.
// Single-term fp16 (y is stored fp16 anyway; GEMM error ~3e-4 matches).
// Tile BM=128, BN=64, BK=32; 8 warps (4 M x 2 N), warp tile 32x32.
// ---------------------------------------------------------------------------
#define BM 128
#define BN 64
#define BK 32
#define KPAD 40

#define MMA_FP16(d, a, b)                                                      \
    asm volatile(                                                              \
        "mma.sync.aligned.m16n8k16.row.col.f32.f16.f16.f32 "                   \
        "{%0,%1,%2,%3}, {%4,%5,%6,%7}, {%8,%9}, {%0,%1,%2,%3};\n"              \
        : "+f"(d[0]), "+f"(d[1]), "+f"(d[2]), "+f"(d[3])                       \
        : "r"(a[0]), "r"(a[1]), "r"(a[2]), "r"(a[3]), "r"(b[0]), "r"(b[1]))

__global__ __launch_bounds__(256, 2) void gemm_fp16_kernel(
    const float* __restrict__ x, const float* __restrict__ W, int M)
{
    __shared__ __half Ah[BM][KPAD];
    __shared__ __half Bh[BN][KPAD];

    const int tid = threadIdx.x;
    const int wid = tid >> 5;
    const int lane = tid & 31;
    const int g = lane >> 2;
    const int tg = lane & 3;
    const int wm = (wid & 3) * 32;
    const int wn = (wid >> 2) * 32;
    const int bm = blockIdx.x * BM;
    const int bn = blockIdx.y * BN;

    float acc[2][4][4];
#pragma unroll
    for (int mi = 0; mi < 2; mi++)
#pragma unroll
        for (int ni = 0; ni < 4; ni++)
#pragma unroll
            for (int c = 0; c < 4; c++) acc[mi][ni][c] = 0.0f;

    const int arow = tid >> 3;        // 0..31, 4 passes of 32 rows
    const int acol = (tid & 7) * 4;   // 0..28
    const int wk = tid >> 4;          // 0..15, 2 passes of 16 k
    const int wn4 = (tid & 15) * 4;   // 0..60

    for (int k0 = 0; k0 < FEAT; k0 += BK) {
        // A tile: fp32 -> fp16, [m][k]
#pragma unroll
        for (int i = 0; i < 4; i++) {
            int r = arow + i * 32;
            float4 v = make_float4(0.f, 0.f, 0.f, 0.f);
            if (bm + r < M)
                v = *(const float4*)(x + (size_t)(bm + r) * FEAT + k0 + acol);
            __half2 p0 = __floats2half2_rn(v.x, v.y);
            __half2 p1 = __floats2half2_rn(v.z, v.w);
            *(uint2*)&Ah[r][acol] = make_uint2(*(uint32_t*)&p0, *(uint32_t*)&p1);
        }
        // B tile: W[k][n] fp32 -> fp16 transposed into [n][k]
#pragma unroll
        for (int i = 0; i < 2; i++) {
            int kk = wk + i * 16;
            float4 v = *(const float4*)(W + (size_t)(k0 + kk) * FEAT + bn + wn4);
            Bh[wn4 + 0][kk] = __float2half_rn(v.x);
            Bh[wn4 + 1][kk] = __float2half_rn(v.y);
            Bh[wn4 + 2][kk] = __float2half_rn(v.z);
            Bh[wn4 + 3][kk] = __float2half_rn(v.w);
        }
        __syncthreads();

#pragma unroll
        for (int ks = 0; ks < BK; ks += 16) {
            uint32_t ah[2][4];
#pragma unroll
            for (int mi = 0; mi < 2; mi++) {
                int r = wm + mi * 16 + g;
                ah[mi][0] = *(uint32_t*)&Ah[r][ks + 2 * tg];
                ah[mi][1] = *(uint32_t*)&Ah[r + 8][ks + 2 * tg];
                ah[mi][2] = *(uint32_t*)&Ah[r][ks + 2 * tg + 8];
                ah[mi][3] = *(uint32_t*)&Ah[r + 8][ks + 2 * tg + 8];
            }
            uint32_t bh[4][2];
#pragma unroll
            for (int ni = 0; ni < 4; ni++) {
                int n = wn + ni * 8 + g;
                bh[ni][0] = *(uint32_t*)&Bh[n][ks + 2 * tg];
                bh[ni][1] = *(uint32_t*)&Bh[n][ks + 2 * tg + 8];
            }
#pragma unroll
            for (int mi = 0; mi < 2; mi++)
#pragma unroll
                for (int ni = 0; ni < 4; ni++)
                    MMA_FP16(acc[mi][ni], ah[mi], bh[ni]);
        }
        __syncthreads();
    }

    // epilogue: y = acc * dinv[row], stored fp16
    __half2* yh2 = (__half2*)g_yh;
#pragma unroll
    for (int mi = 0; mi < 2; mi++) {
        int r0 = bm + wm + mi * 16 + g;
        int r1 = r0 + 8;
        float dv0 = (r0 < M) ? g_dinv[r0] : 0.0f;
        float dv1 = (r1 < M) ? g_dinv[r1] : 0.0f;
#pragma unroll
        for (int ni = 0; ni < 4; ni++) {
            int c = bn + wn + ni * 8 + 2 * tg;
            if (r0 < M)
                yh2[(size_t)r0 * (FEAT / 2) + (c >> 1)] =
                    __floats2half2_rn(acc[mi][ni][0] * dv0, acc[mi][ni][1] * dv0);
            if (r1 < M)
                yh2[(size_t)r1 * (FEAT / 2) + (c >> 1)] =
                    __floats2half2_rn(acc[mi][ni][2] * dv1, acc[mi][ni][3] * dv1);
        }
    }
}

// ---------------------------------------------------------------------------
// Pull aggregation: one warp per dst node, fp16 rows (512 B). Each lane owns
// 8 halves = one uint4 per row. 8x unroll for deep MLP; fp32 accumulation.
// ---------------------------------------------------------------------------
__device__ __forceinline__ void acc_row(float* acc, uint4 u) {
    __half2* h = (__half2*)&u;
#pragma unroll
    for (int q = 0; q < 4; q++) {
        float2 f = __half22float2(h[q]);
        acc[2 * q] += f.x;
        acc[2 * q + 1] += f.y;
    }
}

__global__ __launch_bounds__(256) void pull_kernel(
    float* __restrict__ out, const float* __restrict__ bias, int N)
{
    int warp = (blockIdx.x * blockDim.x + threadIdx.x) >> 5;
    int lane = threadIdx.x & 31;
    if (warp >= N) return;

    int beg = g_off[warp];
    int end = g_off[warp + 1];
    float dv = g_dinv[warp];

    float acc[8];
    {   // self loop
        uint4 u = __ldg((const uint4*)(g_yh + (size_t)warp * FEAT) + lane);
        __half2* h = (__half2*)&u;
#pragma unroll
        for (int q = 0; q < 4; q++) {
            float2 f = __half22float2(h[q]);
            acc[2 * q] = f.x;
            acc[2 * q + 1] = f.y;
        }
    }

    int j = beg;
    for (; j + 8 <= end; j += 8) {
        int s[8];
#pragma unroll
        for (int t = 0; t < 8; t++) s[t] = g_srcs[j + t];
        uint4 u[8];
#pragma unroll
        for (int t = 0; t < 8; t++)
            u[t] = __ldg((const uint4*)(g_yh + (size_t)s[t] * FEAT) + lane);
#pragma unroll
        for (int t = 0; t < 8; t++) acc_row(acc, u[t]);
    }
    for (; j + 2 <= end; j += 2) {
        int s0 = g_srcs[j], s1 = g_srcs[j + 1];
        uint4 u0 = __ldg((const uint4*)(g_yh + (size_t)s0 * FEAT) + lane);
        uint4 u1 = __ldg((const uint4*)(g_yh + (size_t)s1 * FEAT) + lane);
        acc_row(acc, u0);
        acc_row(acc, u1);
    }
    if (j < end) {
        uint4 u0 = __ldg((const uint4*)(g_yh + (size_t)g_srcs[j] * FEAT) + lane);
        acc_row(acc, u0);
    }

    float4 b0 = *(const float4*)(bias + lane * 8);
    float4 b1 = *(const float4*)(bias + lane * 8 + 4);
    float4 o0, o1;
    o0.x = fmaxf(fmaf(acc[0], dv, b0.x), 0.f);
    o0.y = fmaxf(fmaf(acc[1], dv, b0.y), 0.f);
    o0.z = fmaxf(fmaf(acc[2], dv, b0.z), 0.f);
    o0.w = fmaxf(fmaf(acc[3], dv, b0.w), 0.f);
    o1.x = fmaxf(fmaf(acc[4], dv, b1.x), 0.f);
    o1.y = fmaxf(fmaf(acc[5], dv, b1.y), 0.f);
    o1.z = fmaxf(fmaf(acc[6], dv, b1.z), 0.f);
    o1.w = fmaxf(fmaf(acc[7], dv, b1.w), 0.f);

    float* orow = out + (size_t)warp * FEAT + lane * 8;
    *(float4*)orow = o0;
    *(float4*)(orow + 4) = o1;
}

// ---------------------------------------------------------------------------
// Launch
// ---------------------------------------------------------------------------
extern "C" void kernel_launch(void* const* d_in, const int* in_sizes, int n_in,
                              void* d_out, int out_size)
{
    const float* x = (const float*)d_in[0];
    const void*  e = d_in[1];
    const float* W = (const float*)d_in[2];
    const float* b = (const float*)d_in[3];
    float* out = (float*)d_out;

    const int N = in_sizes[0] / FEAT;   // 50000
    const int E = in_sizes[1] / 2;      // 1,600,000

    detect_dtype_kernel<<<1, 256>>>((const int*)e);
    zero_deg_kernel<<<(N + 255) / 256, 256>>>(N);
    count_deg_kernel<<<(E + 255) / 256, 256>>>(e, E);

    int NB = (N + SCB - 1) / SCB;
    block_sum_kernel<<<NB, SCB>>>(N);
    scan_bsum_kernel<<<1, 128>>>(NB);
    scan_final_kernel<<<NB, SCB>>>(N);

    fill_kernel<<<(E + 255) / 256, 256>>>(e, E);

    dim3 ggrid((N + BM - 1) / BM, FEAT / BN);
    gemm_fp16_kernel<<<ggrid, 256>>>(x, W, N);

    int pblocks = (N + 7) / 8;
    pull_kernel<<<pblocks, 256>>>(out, b, N);
}